// round 1
// baseline (speedup 1.0000x reference)
#include <cuda_runtime.h>
#include <math.h>

#define NTOT 65536
#define BG   64
#define NPG  1024
#define ETOT 1048576
#define DD   128
#define KK   512   // NPG/2

// ---------------- scratch (device globals: allocation-free) ----------------
__device__ float g_h[(size_t)NTOT * DD];      // x @ W
__device__ float g_o[(size_t)NTOT * DD];      // accumulated conv output -> relu'd in place
__device__ float g_deg[NTOT];
__device__ float g_dinv[NTOT];
__device__ float g_score[NTOT];

// ---------------- degree ----------------
__global__ void k_deg_init() {
    int i = blockIdx.x * blockDim.x + threadIdx.x;
    if (i < NTOT) g_deg[i] = 1.0f;   // self-loop weight
}

__global__ void k_deg_edges(const int* __restrict__ dst, const float* __restrict__ w) {
    int e = blockIdx.x * blockDim.x + threadIdx.x;
    if (e < ETOT) atomicAdd(&g_deg[dst[e]], w[e]);
}

__global__ void k_dinv() {
    int i = blockIdx.x * blockDim.x + threadIdx.x;
    if (i < NTOT) g_dinv[i] = rsqrtf(fmaxf(g_deg[i], 1e-12f));
}

// ---------------- GEMM: g_h = x @ W  (fp32, 128-row tile, 8x8 blocking) ----------------
#define GEMM_SMEM_BYTES ((DD * DD + 128 * 129) * 4)

__global__ void k_gemm(const float* __restrict__ x, const float* __restrict__ W) {
    extern __shared__ float smem[];
    float* Ws = smem;                 // [128][128]  W[k][c]
    float* Xs = smem + DD * DD;       // [128][129]  padded rows

    int tid = threadIdx.x;            // 256 threads
    int rb  = blockIdx.x * 128;

    const float4* W4  = (const float4*)W;
    float4*       Ws4 = (float4*)Ws;
    #pragma unroll 4
    for (int i = tid; i < 4096; i += 256) Ws4[i] = W4[i];

    const float4* x4 = (const float4*)x;
    #pragma unroll 4
    for (int i = tid; i < 4096; i += 256) {
        int r = i >> 5, j = i & 31;
        float4 v = x4[(size_t)(rb + r) * 32 + j];
        float* dp = &Xs[r * 129 + j * 4];
        dp[0] = v.x; dp[1] = v.y; dp[2] = v.z; dp[3] = v.w;
    }
    __syncthreads();

    int tx = tid & 15;    // col group
    int ty = tid >> 4;    // row group

    float acc[8][8];
    #pragma unroll
    for (int i = 0; i < 8; i++)
        #pragma unroll
        for (int j = 0; j < 8; j++) acc[i][j] = 0.0f;

    #pragma unroll 2
    for (int k = 0; k < 128; k++) {
        float a[8], bq[8];
        #pragma unroll
        for (int i = 0; i < 8; i++) a[i]  = Xs[(ty * 8 + i) * 129 + k];
        #pragma unroll
        for (int j = 0; j < 8; j++) bq[j] = Ws[k * 128 + tx + 16 * j];
        #pragma unroll
        for (int i = 0; i < 8; i++)
            #pragma unroll
            for (int j = 0; j < 8; j++) acc[i][j] += a[i] * bq[j];
    }

    #pragma unroll
    for (int i = 0; i < 8; i++) {
        int row = rb + ty * 8 + i;
        #pragma unroll
        for (int j = 0; j < 8; j++)
            g_h[(size_t)row * DD + tx + 16 * j] = acc[i][j];
    }
}

// ---------------- out init: b + self-loop term ----------------
__global__ void k_init_out(const float* __restrict__ bvec) {
    int t = blockIdx.x * blockDim.x + threadIdx.x;   // NTOT*32 float4 slots
    if (t >= NTOT * 32) return;
    int node = t >> 5, q = t & 31;
    float di = g_dinv[node];
    float c  = di * di;                     // norm of self-loop (w=1)
    float4 hv = ((const float4*)g_h)[t];
    float4 bq = ((const float4*)bvec)[q];
    float4 o;
    o.x = bq.x + c * hv.x; o.y = bq.y + c * hv.y;
    o.z = bq.z + c * hv.z; o.w = bq.w + c * hv.w;
    ((float4*)g_o)[t] = o;
}

// ---------------- edge scatter: warp per edge, vector atomics ----------------
__global__ void k_scatter(const int* __restrict__ src, const int* __restrict__ dst,
                          const float* __restrict__ w) {
    int gt   = blockIdx.x * blockDim.x + threadIdx.x;
    int e    = gt >> 5;
    int lane = gt & 31;
    if (e >= ETOT) return;
    int s = src[e], d = dst[e];
    float nrm = g_dinv[s] * w[e] * g_dinv[d];
    float4 hv = ((const float4*)g_h)[(size_t)s * 32 + lane];
    float4 v  = make_float4(nrm * hv.x, nrm * hv.y, nrm * hv.z, nrm * hv.w);
    float* op = &g_o[(size_t)d * DD + lane * 4];
#if defined(__CUDA_ARCH__) && (__CUDA_ARCH__ >= 900)
    atomicAdd((float4*)op, v);
#else
    atomicAdd(op + 0, v.x); atomicAdd(op + 1, v.y);
    atomicAdd(op + 2, v.z); atomicAdd(op + 3, v.w);
#endif
}

// ---------------- relu + score: warp per node ----------------
__global__ void k_relu_score(const float* __restrict__ p) {
    int gt   = blockIdx.x * blockDim.x + threadIdx.x;
    int node = gt >> 5;
    int lane = gt & 31;
    if (node >= NTOT) return;
    float4* o4 = (float4*)g_o;
    float4 v = o4[(size_t)node * 32 + lane];
    v.x = fmaxf(v.x, 0.0f); v.y = fmaxf(v.y, 0.0f);
    v.z = fmaxf(v.z, 0.0f); v.w = fmaxf(v.w, 0.0f);
    o4[(size_t)node * 32 + lane] = v;
    float4 pv = ((const float4*)p)[lane];
    float hp = v.x * pv.x + v.y * pv.y + v.z * pv.z + v.w * pv.w;
    float pp = pv.x * pv.x + pv.y * pv.y + pv.z * pv.z + pv.w * pv.w;
    #pragma unroll
    for (int off = 16; off > 0; off >>= 1) {
        hp += __shfl_xor_sync(0xFFFFFFFFu, hp, off);
        pp += __shfl_xor_sync(0xFFFFFFFFu, pp, off);
    }
    if (lane == 0) g_score[node] = hp * rsqrtf(pp);
}

// ---------------- top-K threshold + weighted mean (order-invariant) ----------------
__global__ void k_pool(float* __restrict__ out) {
    __shared__ float s_sc[NPG];
    __shared__ float s_sort[NPG];
    __shared__ float s_w[NPG];
    __shared__ float s_part[8 * DD];
    __shared__ int   s_cnt;

    int g = blockIdx.x;
    int t = threadIdx.x;         // 1024 threads
    int base = g * NPG;

    float sc = g_score[base + t];
    s_sc[t] = sc; s_sort[t] = sc;
    if (t == 0) s_cnt = 0;
    __syncthreads();

    // bitonic sort ascending
    for (int k = 2; k <= NPG; k <<= 1) {
        for (int j = k >> 1; j > 0; j >>= 1) {
            int ixj = t ^ j;
            if (ixj > t) {
                float a = s_sort[t], b = s_sort[ixj];
                bool up = ((t & k) == 0);
                if ((a > b) == up) { s_sort[t] = b; s_sort[ixj] = a; }
            }
            __syncthreads();
        }
    }
    float thr = s_sort[NPG - KK];   // 512th largest
    __syncthreads();

    int isgt = (sc > thr);
    if (isgt) atomicAdd(&s_cnt, 1);
    __syncthreads();
    int need_eq = KK - s_cnt;

    float wgt = 0.0f;
    if (isgt) {
        wgt = tanhf(sc);
    } else if (sc == thr) {
        // stable tie-break: lowest indices first (matches jax top_k)
        int r = 0;
        for (int j = 0; j < t; j++) if (s_sc[j] == thr) r++;
        if (r < need_eq) wgt = tanhf(sc);
    }
    s_w[t] = wgt;
    __syncthreads();

    // weighted sum over selected rows: 8 groups x 128 cols
    int grp = t >> 7, c = t & 127;
    float part = 0.0f;
    for (int n = grp; n < NPG; n += 8) {
        float wn = s_w[n];
        if (wn != 0.0f) part += wn * g_o[(size_t)(base + n) * DD + c];
    }
    s_part[grp * DD + c] = part;
    __syncthreads();

    if (t < DD) {
        float s = 0.0f;
        #pragma unroll
        for (int q = 0; q < 8; q++) s += s_part[q * DD + t];
        out[g * DD + t] = s * (1.0f / (float)KK);
    }
}

// ---------------- launch ----------------
extern "C" void kernel_launch(void* const* d_in, const int* in_sizes, int n_in,
                              void* d_out, int out_size) {
    const float* x  = (const float*)d_in[0];
    const float* ew = (const float*)d_in[1];
    const float* W  = (const float*)d_in[2];
    const float* b  = (const float*)d_in[3];
    const float* p  = (const float*)d_in[4];
    const int*   ei = (const int*)d_in[5];
    const int* src = ei;
    const int* dst = ei + ETOT;
    float* out = (float*)d_out;

    cudaFuncSetAttribute(k_gemm, cudaFuncAttributeMaxDynamicSharedMemorySize, GEMM_SMEM_BYTES);

    k_deg_init<<<NTOT / 256, 256>>>();
    k_deg_edges<<<ETOT / 256, 256>>>(dst, ew);
    k_dinv<<<NTOT / 256, 256>>>();

    k_gemm<<<NTOT / 128, 256, GEMM_SMEM_BYTES>>>(x, W);

    k_init_out<<<(NTOT * 32) / 256, 256>>>(b);
    k_scatter<<<(ETOT * 32) / 256, 256>>>(src, dst, ew);
    k_relu_score<<<(NTOT * 32) / 256, 256>>>(p);
    k_pool<<<BG, NPG>>>(out);
}

// round 2
// speedup vs baseline: 1.3263x; 1.3263x over previous
#include <cuda_runtime.h>
#include <math.h>

#define NTOT 65536
#define BG   64
#define NPG  1024
#define ETOT 1048576
#define DD   128
#define KK   512   // NPG/2

// ---------------- scratch (device globals: allocation-free) ----------------
__device__ float g_h[(size_t)NTOT * DD];      // x @ W
__device__ float g_o[(size_t)NTOT * DD];      // conv output (relu'd)
__device__ float g_deg[NTOT];
__device__ float g_dinv[NTOT];
__device__ float g_score[NTOT];
__device__ int   g_cnt[NTOT];
__device__ int   g_off[NTOT + 1];
__device__ int   g_cur[NTOT];
__device__ int   g_bsum[256];
__device__ int   g_bbase[256];
__device__ int2  g_epack[ETOT];               // {src, norm as bits} sorted by dst

// ---------------- degree + counts ----------------
__global__ void k_deg_init() {
    int i = blockIdx.x * blockDim.x + threadIdx.x;
    if (i < NTOT) { g_deg[i] = 1.0f; g_cnt[i] = 0; }   // self-loop weight 1
}

__global__ void k_count(const int* __restrict__ dst, const float* __restrict__ w) {
    int e = blockIdx.x * blockDim.x + threadIdx.x;
    if (e < ETOT) {
        int d = dst[e];
        atomicAdd(&g_deg[d], w[e]);
        atomicAdd(&g_cnt[d], 1);
    }
}

__global__ void k_dinv() {
    int i = blockIdx.x * blockDim.x + threadIdx.x;
    if (i < NTOT) g_dinv[i] = rsqrtf(fmaxf(g_deg[i], 1e-12f));
}

// ---------------- 3-stage exclusive scan of g_cnt -> g_off ----------------
__global__ void k_scan1() {           // 256 blocks x 256 threads
    __shared__ int sm[256];
    int t = threadIdx.x, idx = blockIdx.x * 256 + t;
    int v = g_cnt[idx];
    sm[t] = v;
    __syncthreads();
    for (int d = 1; d < 256; d <<= 1) {
        int u = (t >= d) ? sm[t - d] : 0;
        __syncthreads();
        sm[t] += u;
        __syncthreads();
    }
    g_off[idx] = sm[t] - v;           // local exclusive
    if (t == 255) g_bsum[blockIdx.x] = sm[t];
}

__global__ void k_scan2() {           // 1 block x 256 threads
    __shared__ int sm[256];
    int t = threadIdx.x;
    sm[t] = g_bsum[t];
    __syncthreads();
    for (int d = 1; d < 256; d <<= 1) {
        int u = (t >= d) ? sm[t - d] : 0;
        __syncthreads();
        sm[t] += u;
        __syncthreads();
    }
    g_bbase[t] = (t == 0) ? 0 : sm[t - 1];
}

__global__ void k_scan3() {           // finalize offsets + cursors
    int idx = blockIdx.x * blockDim.x + threadIdx.x;
    if (idx < NTOT) {
        int o = g_off[idx] + g_bbase[idx >> 8];
        g_off[idx] = o;
        g_cur[idx] = o;
    }
    if (idx == 0) g_off[NTOT] = ETOT;
}

// ---------------- fill CSR with packed {src, norm} ----------------
__global__ void k_fill(const int* __restrict__ src, const int* __restrict__ dst,
                       const float* __restrict__ w) {
    int e = blockIdx.x * blockDim.x + threadIdx.x;
    if (e >= ETOT) return;
    int s = src[e], d = dst[e];
    float nrm = g_dinv[s] * w[e] * g_dinv[d];
    int pos = atomicAdd(&g_cur[d], 1);
    g_epack[pos] = make_int2(s, __float_as_int(nrm));
}

// ---------------- GEMM: g_h = x @ W  (fp32, 128x128 tile, 8x8, float4 LDS) ----------------
#define XPAD 132
#define GEMM_SMEM_BYTES ((DD * DD + 128 * XPAD) * 4)

__global__ void k_gemm(const float* __restrict__ x, const float* __restrict__ W) {
    extern __shared__ float smem[];
    float* Ws = smem;                 // [128][128]  W[k][c]
    float* Xs = smem + DD * DD;       // [128][XPAD] rows

    int tid = threadIdx.x;            // 256 threads
    int rb  = blockIdx.x * 128;

    const float4* W4  = (const float4*)W;
    float4*       Ws4 = (float4*)Ws;
    #pragma unroll 4
    for (int i = tid; i < 4096; i += 256) Ws4[i] = W4[i];

    const float4* x4 = (const float4*)x;
    #pragma unroll 4
    for (int i = tid; i < 4096; i += 256) {
        int r = i >> 5, j = i & 31;
        float4 v = x4[(size_t)(rb + r) * 32 + j];
        ((float4*)(Xs + r * XPAD))[j] = v;
    }
    __syncthreads();

    int tx = tid & 15;    // col block: cols tx*8 .. tx*8+7
    int ty = tid >> 4;    // row block: rows ty*8 .. ty*8+7

    float acc[8][8];
    #pragma unroll
    for (int i = 0; i < 8; i++)
        #pragma unroll
        for (int j = 0; j < 8; j++) acc[i][j] = 0.0f;

    for (int k0 = 0; k0 < 128; k0 += 4) {
        float4 av[8];
        #pragma unroll
        for (int i = 0; i < 8; i++)
            av[i] = *(const float4*)&Xs[(ty * 8 + i) * XPAD + k0];

        #pragma unroll
        for (int kk = 0; kk < 4; kk++) {
            int k = k0 + kk;
            float4 b0 = *(const float4*)&Ws[k * 128 + tx * 8];
            float4 b1 = *(const float4*)&Ws[k * 128 + tx * 8 + 4];
            float bq[8] = {b0.x, b0.y, b0.z, b0.w, b1.x, b1.y, b1.z, b1.w};
            #pragma unroll
            for (int i = 0; i < 8; i++) {
                float a = (kk == 0) ? av[i].x : (kk == 1) ? av[i].y
                        : (kk == 2) ? av[i].z : av[i].w;
                #pragma unroll
                for (int j = 0; j < 8; j++) acc[i][j] += a * bq[j];
            }
        }
    }

    #pragma unroll
    for (int i = 0; i < 8; i++) {
        int row = rb + ty * 8 + i;
        float* dp = &g_h[(size_t)row * DD + tx * 8];
        *(float4*)dp       = make_float4(acc[i][0], acc[i][1], acc[i][2], acc[i][3]);
        *(float4*)(dp + 4) = make_float4(acc[i][4], acc[i][5], acc[i][6], acc[i][7]);
    }
}

// ---------------- fused gather: init + aggregate + relu + score ----------------
__global__ void k_gather(const float* __restrict__ bvec, const float* __restrict__ p) {
    int gt   = blockIdx.x * blockDim.x + threadIdx.x;
    int node = gt >> 5;
    int lane = gt & 31;
    if (node >= NTOT) return;

    const float4* h4 = (const float4*)g_h;
    float di = g_dinv[node];
    float c  = di * di;                          // self-loop norm
    float4 hv = h4[(size_t)node * 32 + lane];
    float4 bq = ((const float4*)bvec)[lane];
    float4 acc = make_float4(bq.x + c * hv.x, bq.y + c * hv.y,
                             bq.z + c * hv.z, bq.w + c * hv.w);

    int i0 = g_off[node], i1 = g_off[node + 1];
    if (i0 < i1) {
        int2 pk = g_epack[i0];
        for (int i = i0; i < i1; i++) {
            int2 nx = (i + 1 < i1) ? g_epack[i + 1] : pk;   // prefetch
            float nm = __int_as_float(pk.y);
            float4 v = h4[(size_t)pk.x * 32 + lane];
            acc.x += nm * v.x; acc.y += nm * v.y;
            acc.z += nm * v.z; acc.w += nm * v.w;
            pk = nx;
        }
    }

    acc.x = fmaxf(acc.x, 0.0f); acc.y = fmaxf(acc.y, 0.0f);
    acc.z = fmaxf(acc.z, 0.0f); acc.w = fmaxf(acc.w, 0.0f);
    ((float4*)g_o)[(size_t)node * 32 + lane] = acc;

    float4 pv = ((const float4*)p)[lane];
    float hp = acc.x * pv.x + acc.y * pv.y + acc.z * pv.z + acc.w * pv.w;
    float pp = pv.x * pv.x + pv.y * pv.y + pv.z * pv.z + pv.w * pv.w;
    #pragma unroll
    for (int off = 16; off > 0; off >>= 1) {
        hp += __shfl_xor_sync(0xFFFFFFFFu, hp, off);
        pp += __shfl_xor_sync(0xFFFFFFFFu, pp, off);
    }
    if (lane == 0) g_score[node] = hp * rsqrtf(pp);
}

// ---------------- top-K threshold + weighted mean (order-invariant) ----------------
__global__ void k_pool(float* __restrict__ out) {
    __shared__ float s_sc[NPG];
    __shared__ float s_sort[NPG];
    __shared__ float s_w[NPG];
    __shared__ float s_part[8 * DD];
    __shared__ int   s_cnt;

    int g = blockIdx.x;
    int t = threadIdx.x;         // 1024 threads
    int base = g * NPG;

    float sc = g_score[base + t];
    s_sc[t] = sc; s_sort[t] = sc;
    if (t == 0) s_cnt = 0;
    __syncthreads();

    // bitonic sort ascending
    for (int k = 2; k <= NPG; k <<= 1) {
        for (int j = k >> 1; j > 0; j >>= 1) {
            int ixj = t ^ j;
            if (ixj > t) {
                float a = s_sort[t], b = s_sort[ixj];
                bool up = ((t & k) == 0);
                if ((a > b) == up) { s_sort[t] = b; s_sort[ixj] = a; }
            }
            __syncthreads();
        }
    }
    float thr = s_sort[NPG - KK];   // 512th largest
    __syncthreads();

    int isgt = (sc > thr);
    if (isgt) atomicAdd(&s_cnt, 1);
    __syncthreads();
    int need_eq = KK - s_cnt;

    float wgt = 0.0f;
    if (isgt) {
        wgt = tanhf(sc);
    } else if (sc == thr) {
        // stable tie-break: lowest indices first (matches jax top_k)
        int r = 0;
        for (int j = 0; j < t; j++) if (s_sc[j] == thr) r++;
        if (r < need_eq) wgt = tanhf(sc);
    }
    s_w[t] = wgt;
    __syncthreads();

    // weighted sum over selected rows: 8 groups x 128 cols
    int grp = t >> 7, c = t & 127;
    float part = 0.0f;
    for (int n = grp; n < NPG; n += 8) {
        float wn = s_w[n];
        if (wn != 0.0f) part += wn * g_o[(size_t)(base + n) * DD + c];
    }
    s_part[grp * DD + c] = part;
    __syncthreads();

    if (t < DD) {
        float s = 0.0f;
        #pragma unroll
        for (int q = 0; q < 8; q++) s += s_part[q * DD + t];
        out[g * DD + t] = s * (1.0f / (float)KK);
    }
}

// ---------------- launch ----------------
extern "C" void kernel_launch(void* const* d_in, const int* in_sizes, int n_in,
                              void* d_out, int out_size) {
    const float* x  = (const float*)d_in[0];
    const float* ew = (const float*)d_in[1];
    const float* W  = (const float*)d_in[2];
    const float* b  = (const float*)d_in[3];
    const float* p  = (const float*)d_in[4];
    const int*   ei = (const int*)d_in[5];
    const int* src = ei;
    const int* dst = ei + ETOT;
    float* out = (float*)d_out;

    cudaFuncSetAttribute(k_gemm, cudaFuncAttributeMaxDynamicSharedMemorySize, GEMM_SMEM_BYTES);

    k_deg_init<<<NTOT / 256, 256>>>();
    k_count<<<ETOT / 256, 256>>>(dst, ew);
    k_dinv<<<NTOT / 256, 256>>>();

    k_scan1<<<256, 256>>>();
    k_scan2<<<1, 256>>>();
    k_scan3<<<NTOT / 256, 256>>>();
    k_fill<<<ETOT / 256, 256>>>(src, dst, ew);

    k_gemm<<<NTOT / 128, 256, GEMM_SMEM_BYTES>>>(x, W);

    k_gather<<<(NTOT * 32) / 256, 256>>>(b, p);
    k_pool<<<BG, NPG>>>(out);
}

// round 4
// speedup vs baseline: 1.4128x; 1.0652x over previous
#include <cuda_runtime.h>
#include <cuda_bf16.h>
#include <cstdint>
#include <math.h>

#define NTOT 65536
#define BG   64
#define NPG  1024
#define ETOT 1048576
#define DD   128
#define KK   512   // NPG/2

// ---------------- scratch (device globals: allocation-free) ----------------
__device__ float g_h[(size_t)NTOT * DD];      // agg = A_hat @ x
__device__ float g_o[(size_t)NTOT * DD];      // relu(conv output)
__device__ float g_deg[NTOT];
__device__ float g_dinv[NTOT];
__device__ float g_score[NTOT];
__device__ float g_pinv;
__device__ int   g_cnt[NTOT];
__device__ int   g_off[NTOT + 1];
__device__ int   g_cur[NTOT];
__device__ int   g_bsum[256];
__device__ int   g_bbase[256];
__device__ int2  g_epack[ETOT];               // {src, norm bits} grouped by dst

// ---------------- degree + counts ----------------
__global__ void k_deg_init() {
    int i = blockIdx.x * blockDim.x + threadIdx.x;
    if (i < NTOT) { g_deg[i] = 1.0f; g_cnt[i] = 0; }
}
__global__ void k_count(const int* __restrict__ dst, const float* __restrict__ w) {
    int e = blockIdx.x * blockDim.x + threadIdx.x;
    if (e < ETOT) {
        int d = dst[e];
        atomicAdd(&g_deg[d], w[e]);
        atomicAdd(&g_cnt[d], 1);
    }
}
__global__ void k_dinv() {
    int i = blockIdx.x * blockDim.x + threadIdx.x;
    if (i < NTOT) g_dinv[i] = rsqrtf(fmaxf(g_deg[i], 1e-12f));
}

// ---------------- 3-stage exclusive scan ----------------
__global__ void k_scan1() {
    __shared__ int sm[256];
    int t = threadIdx.x, idx = blockIdx.x * 256 + t;
    int v = g_cnt[idx];
    sm[t] = v; __syncthreads();
    for (int d = 1; d < 256; d <<= 1) {
        int u = (t >= d) ? sm[t - d] : 0;
        __syncthreads(); sm[t] += u; __syncthreads();
    }
    g_off[idx] = sm[t] - v;
    if (t == 255) g_bsum[blockIdx.x] = sm[t];
}
__global__ void k_scan2() {
    __shared__ int sm[256];
    int t = threadIdx.x;
    sm[t] = g_bsum[t]; __syncthreads();
    for (int d = 1; d < 256; d <<= 1) {
        int u = (t >= d) ? sm[t - d] : 0;
        __syncthreads(); sm[t] += u; __syncthreads();
    }
    g_bbase[t] = (t == 0) ? 0 : sm[t - 1];
}
__global__ void k_scan3() {
    int idx = blockIdx.x * blockDim.x + threadIdx.x;
    if (idx < NTOT) {
        int o = g_off[idx] + g_bbase[idx >> 8];
        g_off[idx] = o;
        g_cur[idx] = o;
    }
    if (idx == 0) g_off[NTOT] = ETOT;
}
__global__ void k_fill(const int* __restrict__ src, const int* __restrict__ dst,
                       const float* __restrict__ w) {
    int e = blockIdx.x * blockDim.x + threadIdx.x;
    if (e >= ETOT) return;
    int s = src[e], d = dst[e];
    float nrm = g_dinv[s] * w[e] * g_dinv[d];
    int pos = atomicAdd(&g_cur[d], 1);
    g_epack[pos] = make_int2(s, __float_as_int(nrm));
}

// ---------------- gather on x: agg = A_hat @ x (self-loop included) ----------------
__global__ void k_gather(const float* __restrict__ x) {
    int gt   = blockIdx.x * blockDim.x + threadIdx.x;
    int node = gt >> 5;
    int lane = gt & 31;
    if (node >= NTOT) return;

    const float4* x4 = (const float4*)x;
    float di = g_dinv[node];
    float c  = di * di;
    float4 xv = x4[(size_t)node * 32 + lane];
    float4 acc = make_float4(c * xv.x, c * xv.y, c * xv.z, c * xv.w);

    int i0 = g_off[node], i1 = g_off[node + 1];
    for (int base = i0; base < i1; base += 32) {
        int nload = i1 - base; if (nload > 32) nload = 32;
        int2 pk = make_int2(0, 0);
        if (lane < nload) pk = g_epack[base + lane];
        int j = 0;
        for (; j + 4 <= nload; j += 4) {
            #pragma unroll
            for (int u = 0; u < 4; u++) {
                int   s  = __shfl_sync(0xFFFFFFFFu, pk.x, j + u);
                float nm = __int_as_float(__shfl_sync(0xFFFFFFFFu, pk.y, j + u));
                float4 v = x4[(size_t)s * 32 + lane];
                acc.x += nm * v.x; acc.y += nm * v.y;
                acc.z += nm * v.z; acc.w += nm * v.w;
            }
        }
        for (; j < nload; j++) {
            int   s  = __shfl_sync(0xFFFFFFFFu, pk.x, j);
            float nm = __int_as_float(__shfl_sync(0xFFFFFFFFu, pk.y, j));
            float4 v = x4[(size_t)s * 32 + lane];
            acc.x += nm * v.x; acc.y += nm * v.y;
            acc.z += nm * v.z; acc.w += nm * v.w;
        }
    }
    ((float4*)g_h)[(size_t)node * 32 + lane] = acc;
}

// ---------------- p norm ----------------
__global__ void k_pnorm(const float* __restrict__ p) {
    int lane = threadIdx.x;
    float4 pv = ((const float4*)p)[lane];
    float pp = pv.x * pv.x + pv.y * pv.y + pv.z * pv.z + pv.w * pv.w;
    #pragma unroll
    for (int off = 16; off > 0; off >>= 1) pp += __shfl_xor_sync(0xFFFFFFFFu, pp, off);
    if (lane == 0) g_pinv = rsqrtf(pp);
}

// ========== tensor-core GEMM (mma.sync bf16-split): out = relu(agg@W + b), score ==========
#define AP 132                         // bf16 pitch per row (pad vs bank conflicts)
#define SM_A_HI 0
#define SM_A_LO (128 * AP)
#define SM_B_HI (2 * 128 * AP)
#define SM_B_LO (3 * 128 * AP)
#define SM_BF16_ELEMS (4 * 128 * AP)
#define SM_F_OFF (SM_BF16_ELEMS * 2)   // byte offset of float area
#define GTC_SMEM (SM_F_OFF + 2 * DD * 4)

__device__ __forceinline__ void bf16_split(float v, __nv_bfloat16& hi, __nv_bfloat16& lo) {
    hi = __float2bfloat16_rn(v);
    lo = __float2bfloat16_rn(v - __bfloat162float(hi));
}

__device__ __forceinline__ void mma_bf16(float* c, uint32_t a0, uint32_t a1, uint32_t a2,
                                         uint32_t a3, uint32_t b0, uint32_t b1) {
    asm volatile(
        "mma.sync.aligned.m16n8k16.row.col.f32.bf16.bf16.f32 "
        "{%0,%1,%2,%3}, {%4,%5,%6,%7}, {%8,%9}, {%0,%1,%2,%3};"
        : "+f"(c[0]), "+f"(c[1]), "+f"(c[2]), "+f"(c[3])
        : "r"(a0), "r"(a1), "r"(a2), "r"(a3), "r"(b0), "r"(b1));
}

__global__ __launch_bounds__(256, 1) void k_gemm_mma(const float* __restrict__ W,
                                                     const float* __restrict__ bvec,
                                                     const float* __restrict__ pvec) {
    extern __shared__ __nv_bfloat16 smb[];
    __nv_bfloat16* Ah = smb + SM_A_HI;
    __nv_bfloat16* Al = smb + SM_A_LO;
    __nv_bfloat16* Bh = smb + SM_B_HI;
    __nv_bfloat16* Bl = smb + SM_B_LO;
    float* bs = (float*)((char*)smb + SM_F_OFF);
    float* ps = bs + DD;

    int tid = threadIdx.x;
    int rb  = blockIdx.x * 128;

    // stage A = g_h rows [rb, rb+128) as bf16 hi/lo
    for (int i = tid; i < 128 * 32; i += 256) {
        int r = i >> 5, q = i & 31;
        float4 v = *(const float4*)&g_h[(size_t)(rb + r) * DD + q * 4];
        __nv_bfloat16 h0, l0, h1, l1, h2, l2, h3, l3;
        bf16_split(v.x, h0, l0); bf16_split(v.y, h1, l1);
        bf16_split(v.z, h2, l2); bf16_split(v.w, h3, l3);
        __nv_bfloat16* ah = &Ah[r * AP + q * 4];
        __nv_bfloat16* al = &Al[r * AP + q * 4];
        ah[0] = h0; ah[1] = h1; ah[2] = h2; ah[3] = h3;
        al[0] = l0; al[1] = l1; al[2] = l2; al[3] = l3;
    }
    // stage B = W^T ([n][k]) as bf16 hi/lo
    for (int i = tid; i < 128 * 32; i += 256) {
        int k = i >> 5, q = i & 31;
        float4 v = *(const float4*)&W[(size_t)k * DD + q * 4];
        float vv[4] = {v.x, v.y, v.z, v.w};
        #pragma unroll
        for (int j = 0; j < 4; j++) {
            __nv_bfloat16 hi, lo;
            bf16_split(vv[j], hi, lo);
            Bh[(q * 4 + j) * AP + k] = hi;
            Bl[(q * 4 + j) * AP + k] = lo;
        }
    }
    if (tid < DD) { bs[tid] = bvec[tid]; ps[tid] = pvec[tid]; }
    __syncthreads();

    int w  = tid >> 5;
    int l  = tid & 31;
    int qr = l >> 2;     // 0..7
    int qc = l & 3;      // 0..3

    float acc[16][4];
    #pragma unroll
    for (int t = 0; t < 16; t++)
        #pragma unroll
        for (int j = 0; j < 4; j++) acc[t][j] = 0.0f;

    const __nv_bfloat16* arow0 = Ah + (w * 16 + qr) * AP;
    const __nv_bfloat16* arow1 = arow0 + 8 * AP;
    const __nv_bfloat16* alrow0 = Al + (w * 16 + qr) * AP;
    const __nv_bfloat16* alrow1 = alrow0 + 8 * AP;

    #pragma unroll
    for (int ks = 0; ks < 8; ks++) {
        int k0 = ks * 16;
        uint32_t ah0 = *(const uint32_t*)(arow0  + k0 + qc * 2);
        uint32_t ah1 = *(const uint32_t*)(arow1  + k0 + qc * 2);
        uint32_t ah2 = *(const uint32_t*)(arow0  + k0 + 8 + qc * 2);
        uint32_t ah3 = *(const uint32_t*)(arow1  + k0 + 8 + qc * 2);
        uint32_t al0 = *(const uint32_t*)(alrow0 + k0 + qc * 2);
        uint32_t al1 = *(const uint32_t*)(alrow1 + k0 + qc * 2);
        uint32_t al2 = *(const uint32_t*)(alrow0 + k0 + 8 + qc * 2);
        uint32_t al3 = *(const uint32_t*)(alrow1 + k0 + 8 + qc * 2);

        #pragma unroll
        for (int t = 0; t < 16; t++) {
            const __nv_bfloat16* brow = Bh + (t * 8 + qr) * AP;
            const __nv_bfloat16* browl = Bl + (t * 8 + qr) * AP;
            uint32_t bh0 = *(const uint32_t*)(brow  + k0 + qc * 2);
            uint32_t bh1 = *(const uint32_t*)(brow  + k0 + 8 + qc * 2);
            uint32_t bl0 = *(const uint32_t*)(browl + k0 + qc * 2);
            uint32_t bl1 = *(const uint32_t*)(browl + k0 + 8 + qc * 2);
            mma_bf16(acc[t], ah0, ah1, ah2, ah3, bh0, bh1);
            mma_bf16(acc[t], ah0, ah1, ah2, ah3, bl0, bl1);
            mma_bf16(acc[t], al0, al1, al2, al3, bh0, bh1);
        }
    }

    // epilogue: bias + relu + store g_o + score
    int r0 = rb + w * 16 + qr;
    int r1 = r0 + 8;
    float s0 = 0.0f, s1 = 0.0f;
    #pragma unroll
    for (int t = 0; t < 16; t++) {
        int c0 = t * 8 + qc * 2;
        float b0 = bs[c0], b1 = bs[c0 + 1];
        float p0 = ps[c0], p1 = ps[c0 + 1];
        float v00 = fmaxf(acc[t][0] + b0, 0.0f);
        float v01 = fmaxf(acc[t][1] + b1, 0.0f);
        float v10 = fmaxf(acc[t][2] + b0, 0.0f);
        float v11 = fmaxf(acc[t][3] + b1, 0.0f);
        *(float2*)&g_o[(size_t)r0 * DD + c0] = make_float2(v00, v01);
        *(float2*)&g_o[(size_t)r1 * DD + c0] = make_float2(v10, v11);
        s0 += v00 * p0 + v01 * p1;
        s1 += v10 * p0 + v11 * p1;
    }
    s0 += __shfl_xor_sync(0xFFFFFFFFu, s0, 1);
    s0 += __shfl_xor_sync(0xFFFFFFFFu, s0, 2);
    s1 += __shfl_xor_sync(0xFFFFFFFFu, s1, 1);
    s1 += __shfl_xor_sync(0xFFFFFFFFu, s1, 2);
    if (qc == 0) {
        float pin = g_pinv;
        g_score[r0] = s0 * pin;
        g_score[r1] = s1 * pin;
    }
}

// ---------------- top-K threshold + weighted mean (order-invariant) ----------------
__global__ void k_pool(float* __restrict__ out) {
    __shared__ float s_sc[NPG];
    __shared__ float s_sort[NPG];
    __shared__ float s_w[NPG];
    __shared__ float s_part[8 * DD];
    __shared__ int   s_cnt;

    int g = blockIdx.x;
    int t = threadIdx.x;
    int base = g * NPG;

    float sc = g_score[base + t];
    s_sc[t] = sc; s_sort[t] = sc;
    if (t == 0) s_cnt = 0;
    __syncthreads();

    for (int k = 2; k <= NPG; k <<= 1) {
        for (int j = k >> 1; j > 0; j >>= 1) {
            int ixj = t ^ j;
            if (ixj > t) {
                float a = s_sort[t], b = s_sort[ixj];
                bool up = ((t & k) == 0);
                if ((a > b) == up) { s_sort[t] = b; s_sort[ixj] = a; }
            }
            __syncthreads();
        }
    }
    float thr = s_sort[NPG - KK];
    __syncthreads();

    int isgt = (sc > thr);
    if (isgt) atomicAdd(&s_cnt, 1);
    __syncthreads();
    int need_eq = KK - s_cnt;

    float wgt = 0.0f;
    if (isgt) {
        wgt = tanhf(sc);
    } else if (sc == thr) {
        int r = 0;
        for (int j = 0; j < t; j++) if (s_sc[j] == thr) r++;
        if (r < need_eq) wgt = tanhf(sc);
    }
    s_w[t] = wgt;
    __syncthreads();

    int grp = t >> 7, c = t & 127;
    float part = 0.0f;
    for (int n = grp; n < NPG; n += 8) {
        float wn = s_w[n];
        if (wn != 0.0f) part += wn * g_o[(size_t)(base + n) * DD + c];
    }
    s_part[grp * DD + c] = part;
    __syncthreads();

    if (t < DD) {
        float s = 0.0f;
        #pragma unroll
        for (int q = 0; q < 8; q++) s += s_part[q * DD + t];
        out[g * DD + t] = s * (1.0f / (float)KK);
    }
}

// ---------------- launch ----------------
extern "C" void kernel_launch(void* const* d_in, const int* in_sizes, int n_in,
                              void* d_out, int out_size) {
    const float* x  = (const float*)d_in[0];
    const float* ew = (const float*)d_in[1];
    const float* W  = (const float*)d_in[2];
    const float* b  = (const float*)d_in[3];
    const float* p  = (const float*)d_in[4];
    const int*   ei = (const int*)d_in[5];
    const int* src = ei;
    const int* dst = ei + ETOT;
    float* out = (float*)d_out;

    static int s_attr_done = 0;
    if (!s_attr_done) {
        cudaFuncSetAttribute(k_gemm_mma, cudaFuncAttributeMaxDynamicSharedMemorySize, GTC_SMEM);
        s_attr_done = 1;
    }

    k_deg_init<<<NTOT / 256, 256>>>();
    k_count<<<ETOT / 256, 256>>>(dst, ew);
    k_dinv<<<NTOT / 256, 256>>>();

    k_scan1<<<256, 256>>>();
    k_scan2<<<1, 256>>>();
    k_scan3<<<NTOT / 256, 256>>>();
    k_fill<<<ETOT / 256, 256>>>(src, dst, ew);

    k_gather<<<(NTOT * 32) / 256, 256>>>(x);
    k_pnorm<<<1, 32>>>(p);

    k_gemm_mma<<<NTOT / 128, 256, GTC_SMEM>>>(W, b, p);
    k_pool<<<BG, NPG>>>(out);
}